// round 16
// baseline (speedup 1.0000x reference)
#include <cuda_runtime.h>
#include <cuda_fp16.h>
#include <mma.h>

#define N_NODES 100000
#define N_EDGES 1600000
#define C 64
#define LDA 136   // halves; 272B row stride
#define LDB 72    // halves; 144B row stride
#define LDO 68    // floats; 272B row stride (aliases A region)
#define MMA_ROWS 128
#define MMA_THREADS 256

#define SA_BYTES (MMA_ROWS * LDA * 2)          // 34816
#define SB_BYTES (128 * LDB * 2)               // 18432
#define SMEM_WMMA (SA_BYTES + SB_BYTES + (64 * 3 + MMA_ROWS) * 4)  // 54528

// ---------------- scratch (device globals; cnt restored to 0 by cleanup) ----------------
__device__ __align__(16) __half g_h16[N_NODES * C];
__device__ __align__(16) __half g_agg16[N_NODES * C];
__device__ __align__(16) __half g_wc[3][128 * 64];
__device__ float g_ideg[N_NODES];
__device__ int g_cnt[N_NODES];
__device__ int g_row_ptr[N_NODES + 1];
__device__ int g_cursor[N_NODES];
__device__ int g_csr_src[N_EDGES];

// ---------------- launch 1: hist + x->fp16 + weight prep ----------------
#define NB_EDGE_K ((N_EDGES + 255) / 256)
#define NB_CVT_K  ((N_NODES * C / 4 + 255) / 256)
#define NB_W_K    ((3 * 8192 + 255) / 256)
__global__ void hist_prep_kernel(const int* __restrict__ dst, int* __restrict__ cnt,
                                 const float* __restrict__ x, __half* __restrict__ h16,
                                 const float* __restrict__ w1_0, const float* __restrict__ w2_0,
                                 const float* __restrict__ w1_1, const float* __restrict__ w2_1,
                                 const float* __restrict__ w1_2, const float* __restrict__ w2_2,
                                 __half* __restrict__ wc) {
    int b = blockIdx.x;
    if (b < NB_EDGE_K) {
        int e = b * 256 + threadIdx.x;
        if (e < N_EDGES) atomicAdd(&cnt[dst[e]], 1);
    } else if (b < NB_EDGE_K + NB_CVT_K) {
        int i = (b - NB_EDGE_K) * 256 + threadIdx.x;
        if (i < N_NODES * C / 4) {
            float4 v = ((const float4*)x)[i];
            __half2 p[2];
            p[0] = __floats2half2_rn(v.x, v.y);
            p[1] = __floats2half2_rn(v.z, v.w);
            ((uint2*)h16)[i] = *(uint2*)p;
        }
    } else {
        int i = (b - NB_EDGE_K - NB_CVT_K) * 256 + threadIdx.x;
        if (i < 3 * 8192) {
            int l = i >> 13;
            int r = i & 8191;
            int k = r >> 6, n = r & 63;
            const float* w1 = (l == 0) ? w1_0 : (l == 1) ? w1_1 : w1_2;
            const float* w2 = (l == 0) ? w2_0 : (l == 1) ? w2_1 : w2_2;
            float v = (k < 64) ? w1[n * 64 + k] : w2[n * 64 + (k - 64)];
            wc[l * 8192 + k * 64 + n] = __float2half(v);
        }
    }
}

// ---------------- launch 2: single-block scan -> row_ptr, cursor, ideg ----------------
__global__ __launch_bounds__(1024) void scan_kernel(
    const int* __restrict__ cnt, int* __restrict__ row_ptr,
    int* __restrict__ cursor, float* __restrict__ ideg)
{
    __shared__ int part[1024];
    const int t = threadIdx.x;
    const int CH = (N_NODES + 1023) / 1024;
    int begin = t * CH;
    int end = begin + CH; if (end > N_NODES) end = N_NODES;
    int s = 0;
    for (int i = begin; i < end; i++) s += cnt[i];
    part[t] = s;
    __syncthreads();
    for (int off = 1; off < 1024; off <<= 1) {
        int u = (t >= off) ? part[t - off] : 0;
        __syncthreads();
        part[t] += u;
        __syncthreads();
    }
    int run = part[t] - s;
    for (int i = begin; i < end; i++) {
        int c = cnt[i];
        row_ptr[i] = run;
        cursor[i]  = run;
        ideg[i] = 1.0f / (float)(c > 1 ? c : 1);
        run += c;
    }
    if (t == 1023) row_ptr[N_NODES] = part[1023];
}

// ---------------- launch 3: CSR fill (4 edges/thread, measured best) ----------------
__global__ void fill_kernel(const int* __restrict__ src, const int* __restrict__ dst,
                            int* __restrict__ cursor, int* __restrict__ csr_src) {
    int base = (blockIdx.x * blockDim.x + threadIdx.x) * 4;
    #pragma unroll
    for (int u = 0; u < 4; u++) {
        int e = base + u;
        if (e < N_EDGES) {
            int pos = atomicAdd(&cursor[dst[e]], 1);
            csr_src[pos] = src[e];
        }
    }
}

// ---------------- cleanup: restore cnt==0 for next graph replay ----------------
__global__ void cleanup_kernel(int* __restrict__ cnt) {
    int i = blockIdx.x * blockDim.x + threadIdx.x;
    if (i < N_NODES) cnt[i] = 0;
}

// ---------------- agg: fp16 pairwise hadd2 -> fp32 accumulate (issue-bound fix) --------
__device__ __forceinline__ void accum_pair(float* a, uint4 r0, uint4 r1) {
    __half2* p0 = (__half2*)&r0;
    __half2* p1 = (__half2*)&r1;
    #pragma unroll
    for (int i = 0; i < 4; i++) {
        float2 f = __half22float2(__hadd2(p0[i], p1[i]));
        a[2 * i]     += f.x;
        a[2 * i + 1] += f.y;
    }
}
__device__ __forceinline__ void accum_one(float* a, uint4 r) {
    __half2* p = (__half2*)&r;
    #pragma unroll
    for (int i = 0; i < 4; i++) {
        float2 f = __half22float2(p[i]);
        a[2 * i]     += f.x;
        a[2 * i + 1] += f.y;
    }
}

__global__ __launch_bounds__(256) void agg_f16_kernel(
    const __half* __restrict__ h16,
    const int* __restrict__ row_ptr, const int* __restrict__ csr_src,
    const float* __restrict__ ideg, __half* __restrict__ agg16)
{
    const int node = blockIdx.x * 32 + (threadIdx.x >> 3);
    const int c8 = (threadIdx.x & 7) << 3;
    if (node >= N_NODES) return;

    const int beg = __ldg(&row_ptr[node]);
    const int end = __ldg(&row_ptr[node + 1]);

    float a0[8], a1[8], a2[8], a3[8];
    #pragma unroll
    for (int i = 0; i < 8; i++) { a0[i] = a1[i] = a2[i] = a3[i] = 0.f; }

    int j = beg;
    for (; j + 7 < end; j += 8) {
        int s0 = __ldg(&csr_src[j + 0]);
        int s1 = __ldg(&csr_src[j + 1]);
        int s2 = __ldg(&csr_src[j + 2]);
        int s3 = __ldg(&csr_src[j + 3]);
        int s4 = __ldg(&csr_src[j + 4]);
        int s5 = __ldg(&csr_src[j + 5]);
        int s6 = __ldg(&csr_src[j + 6]);
        int s7 = __ldg(&csr_src[j + 7]);
        uint4 r0 = *(const uint4*)(h16 + s0 * C + c8);
        uint4 r1 = *(const uint4*)(h16 + s1 * C + c8);
        uint4 r2 = *(const uint4*)(h16 + s2 * C + c8);
        uint4 r3 = *(const uint4*)(h16 + s3 * C + c8);
        uint4 r4 = *(const uint4*)(h16 + s4 * C + c8);
        uint4 r5 = *(const uint4*)(h16 + s5 * C + c8);
        uint4 r6 = *(const uint4*)(h16 + s6 * C + c8);
        uint4 r7 = *(const uint4*)(h16 + s7 * C + c8);
        accum_pair(a0, r0, r1);
        accum_pair(a1, r2, r3);
        accum_pair(a2, r4, r5);
        accum_pair(a3, r6, r7);
    }
    for (; j + 1 < end; j += 2) {
        int s0 = __ldg(&csr_src[j + 0]);
        int s1 = __ldg(&csr_src[j + 1]);
        uint4 r0 = *(const uint4*)(h16 + s0 * C + c8);
        uint4 r1 = *(const uint4*)(h16 + s1 * C + c8);
        accum_pair(a0, r0, r1);
    }
    if (j < end) {
        int s0 = __ldg(&csr_src[j]);
        uint4 r0 = *(const uint4*)(h16 + s0 * C + c8);
        accum_one(a0, r0);
    }

    const float id = __ldg(&ideg[node]);
    __half2 outp[4];
    #pragma unroll
    for (int i = 0; i < 4; i++) {
        float x0 = (a0[2 * i]     + a1[2 * i]     + a2[2 * i]     + a3[2 * i])     * id;
        float x1 = (a0[2 * i + 1] + a1[2 * i + 1] + a2[2 * i + 1] + a3[2 * i + 1]) * id;
        outp[i] = __floats2half2_rn(x0, x1);
    }
    *(uint4*)(agg16 + node * C + c8) = *(uint4*)outp;
}

// ---------------- tensor-core fused layer (WMMA) ----------------
// __launch_bounds__(256, 3): cap regs (~85) so 3 blocks/SM co-reside (smem allows 4).
// Theory: ptxas register ballooning on the unrolled fragment chain -> 1 block/SM ->
// 782 serial latency-chain waves = the inferred ~82us/layer. 3x occupancy collapses it.
__global__ __launch_bounds__(MMA_THREADS, 3) void sage_wmma_kernel(
    const __half* __restrict__ h16, const __half* __restrict__ agg16,
    const __half* __restrict__ wc,
    const float* __restrict__ b2,
    const float* __restrict__ bn_g, const float* __restrict__ bn_b,
    const float* __restrict__ bn_m, const float* __restrict__ bn_v,
    float* __restrict__ out32, __half* __restrict__ out16,
    int apply_bn, int write32)
{
    extern __shared__ __align__(16) char dsmem[];
    __half* sa = (__half*)dsmem;
    __half* sb = (__half*)(dsmem + SA_BYTES);
    float* sbias = (float*)(dsmem + SA_BYTES + SB_BYTES);
    float* ssc   = sbias + 64;
    float* sbs   = ssc + 64;
    float* snorm = sbs + 64;
    float* so = reinterpret_cast<float*>(sa);

    const int t = threadIdx.x;
    const int warp = t >> 5;
    const int node0 = blockIdx.x * MMA_ROWS;

    for (int i = t; i < 1024; i += MMA_THREADS) {
        int k = i >> 3, c8 = (i & 7) << 3;
        *(uint4*)&sb[k * LDB + c8] = *(const uint4*)&wc[k * 64 + c8];
    }
    if (t < 64) {
        sbias[t] = b2[t];
        if (apply_bn) {
            float sc = bn_g[t] * rsqrtf(bn_v[t] + 1e-5f);
            ssc[t] = sc;
            sbs[t] = bn_b[t] - bn_m[t] * sc;
        }
    }
    for (int i = t; i < MMA_ROWS * 16; i += MMA_THREADS) {
        int row = i >> 4, c8 = (i & 15) << 3;
        int node = node0 + row;
        uint4 v = make_uint4(0, 0, 0, 0);
        if (node < N_NODES)
            v = (c8 < 64) ? *(const uint4*)&h16[node * C + c8]
                          : *(const uint4*)&agg16[node * C + c8 - 64];
        *(uint4*)&sa[row * LDA + c8] = v;
    }
    __syncthreads();

    using namespace nvcuda;
    wmma::fragment<wmma::accumulator, 16, 16, 16, float> acc[4];
    #pragma unroll
    for (int n = 0; n < 4; n++) wmma::fill_fragment(acc[n], 0.0f);

    const int m0 = warp * 16;
    #pragma unroll
    for (int kc = 0; kc < 8; kc++) {
        const int k0 = kc * 16;
        wmma::fragment<wmma::matrix_a, 16, 16, 16, __half, wmma::row_major> af;
        wmma::load_matrix_sync(af, sa + m0 * LDA + k0, LDA);
        #pragma unroll
        for (int n = 0; n < 4; n++) {
            wmma::fragment<wmma::matrix_b, 16, 16, 16, __half, wmma::row_major> bf;
            wmma::load_matrix_sync(bf, sb + k0 * LDB + n * 16, LDB);
            wmma::mma_sync(acc[n], af, bf, acc[n]);
        }
    }

    #pragma unroll
    for (int n = 0; n < 4; n++)
        wmma::store_matrix_sync(so + m0 * LDO + n * 16, acc[n], LDO, wmma::mem_row_major);

    {
        int row = t >> 1, halfsel = t & 1;
        float s = 0.f;
        #pragma unroll
        for (int c = 0; c < 32; c++) {
            int col = halfsel * 32 + c;
            float v = so[row * LDO + col] + sbias[col];
            s = fmaf(v, v, s);
        }
        s += __shfl_xor_sync(0xffffffffu, s, 1);
        if (halfsel == 0) snorm[row] = 1.0f / fmaxf(sqrtf(s), 1e-12f);
    }
    __syncthreads();

    #pragma unroll
    for (int it = 0; it < 8; it++) {
        int i = t + MMA_THREADS * it;
        int row = i >> 4;
        int c4 = (i & 15) << 2;
        int node = node0 + row;
        if (node >= N_NODES) continue;
        float sc = snorm[row];
        float v0 = (so[row * LDO + c4 + 0] + sbias[c4 + 0]) * sc;
        float v1 = (so[row * LDO + c4 + 1] + sbias[c4 + 1]) * sc;
        float v2 = (so[row * LDO + c4 + 2] + sbias[c4 + 2]) * sc;
        float v3 = (so[row * LDO + c4 + 3] + sbias[c4 + 3]) * sc;
        if (apply_bn) {
            v0 = fmaxf(fmaf(v0, ssc[c4 + 0], sbs[c4 + 0]), 0.f);
            v1 = fmaxf(fmaf(v1, ssc[c4 + 1], sbs[c4 + 1]), 0.f);
            v2 = fmaxf(fmaf(v2, ssc[c4 + 2], sbs[c4 + 2]), 0.f);
            v3 = fmaxf(fmaf(v3, ssc[c4 + 3], sbs[c4 + 3]), 0.f);
        }
        if (write32) {
            *(float4*)&out32[node * C + c4] = make_float4(v0, v1, v2, v3);
        } else {
            __half2 q[2];
            q[0] = __floats2half2_rn(v0, v1);
            q[1] = __floats2half2_rn(v2, v3);
            *(uint2*)&out16[node * C + c4] = *(uint2*)q;
        }
    }
}

// ---------------- host ----------------
extern "C" void kernel_launch(void* const* d_in, const int* in_sizes, int n_in,
                              void* d_out, int out_size) {
    const float* x    = (const float*)d_in[0];
    const int*   esrc = (const int*)d_in[1];
    const int*   edst = (const int*)d_in[2];

    int iw1[3], iw2[3], ib2[3], ibn[2][4];
    if (n_in > 6 && in_sizes[6] == 4096) {
        for (int l = 0; l < 3; l++) { iw1[l] = 3 + 3 * l; iw2[l] = 4 + 3 * l; ib2[l] = 5 + 3 * l; }
        for (int l = 0; l < 2; l++)
            for (int j = 0; j < 4; j++) ibn[l][j] = 12 + 4 * l + j;
    } else {
        iw1[0] = 3;  iw2[0] = 4;  ib2[0] = 5;
        for (int j = 0; j < 4; j++) ibn[0][j] = 6 + j;
        iw1[1] = 10; iw2[1] = 11; ib2[1] = 12;
        for (int j = 0; j < 4; j++) ibn[1][j] = 13 + j;
        iw1[2] = 17; iw2[2] = 18; ib2[2] = 19;
    }

    __half *h16, *agg16, *wc;
    float *ideg;
    int *cnt, *row_ptr, *cursor, *csr_src;
    cudaGetSymbolAddress((void**)&h16,     g_h16);
    cudaGetSymbolAddress((void**)&agg16,   g_agg16);
    cudaGetSymbolAddress((void**)&wc,      g_wc);
    cudaGetSymbolAddress((void**)&ideg,    g_ideg);
    cudaGetSymbolAddress((void**)&cnt,     g_cnt);
    cudaGetSymbolAddress((void**)&row_ptr, g_row_ptr);
    cudaGetSymbolAddress((void**)&cursor,  g_cursor);
    cudaGetSymbolAddress((void**)&csr_src, g_csr_src);

    cudaFuncSetAttribute(sage_wmma_kernel,
                         cudaFuncAttributeMaxDynamicSharedMemorySize, SMEM_WMMA);

    const int NB_HP   = NB_EDGE_K + NB_CVT_K + NB_W_K;
    const int NB_FILL = (N_EDGES / 4 + 255) / 256;
    const int NB_AGG  = (N_NODES + 31) / 32;
    const int NB_MMA  = (N_NODES + MMA_ROWS - 1) / MMA_ROWS;
    const int NB_NODE = (N_NODES + 255) / 256;

    // launch 1: hist (cnt==0: static init + trailing cleanup) + x->fp16 + wconv
    hist_prep_kernel<<<NB_HP, 256>>>(edst, cnt, x, h16,
                                     (const float*)d_in[iw1[0]], (const float*)d_in[iw2[0]],
                                     (const float*)d_in[iw1[1]], (const float*)d_in[iw2[1]],
                                     (const float*)d_in[iw1[2]], (const float*)d_in[iw2[2]],
                                     wc);
    // launch 2: scan
    scan_kernel<<<1, 1024>>>(cnt, row_ptr, cursor, ideg);
    // launch 3: fill
    fill_kernel<<<NB_FILL, 256>>>(esrc, edst, cursor, csr_src);

    // launches 4..9: 3 x (agg, wmma). launch 4 == agg layer 0 (profiled slot).
    for (int l = 0; l < 3; l++) {
        agg_f16_kernel<<<NB_AGG, 256>>>(h16, row_ptr, csr_src, ideg, agg16);
        int has_bn = (l < 2);
        sage_wmma_kernel<<<NB_MMA, MMA_THREADS, SMEM_WMMA>>>(
            h16, agg16, wc + l * 128 * 64,
            (const float*)d_in[ib2[l]],
            has_bn ? (const float*)d_in[ibn[l][0]] : (const float*)d_in[ib2[l]],
            has_bn ? (const float*)d_in[ibn[l][1]] : (const float*)d_in[ib2[l]],
            has_bn ? (const float*)d_in[ibn[l][2]] : (const float*)d_in[ib2[l]],
            has_bn ? (const float*)d_in[ibn[l][3]] : (const float*)d_in[ib2[l]],
            (float*)d_out, h16, has_bn, (l == 2) ? 1 : 0);
    }

    // launch 10: restore cnt==0 for next graph replay
    cleanup_kernel<<<NB_NODE, 256>>>(cnt);
}